// round 3
// baseline (speedup 1.0000x reference)
#include <cuda_runtime.h>
#include <cuda_bf16.h>
#include <cstdint>

#define N_NODES  50000
#define N_EDGES  800000
#define HID      96
#define OUT_DIM  32
#define N_GRAPHS 256

// ---------------- scratch (static device globals; no allocation) ----------------
__device__ __align__(128) float g_dis[N_NODES];            // deg -> d^{-1/2}
__device__ __align__(128) float g_tmp [N_NODES * HID];     // h @ W (pre-scatter)
__device__ __align__(128) float g_bufA[N_NODES * HID];     // layer outputs (ping)
__device__ __align__(128) float g_bufB[N_NODES * HID];     // layer outputs (pong)
__device__ __align__(128) float g_pool[N_GRAPHS * HID];    // per-graph feature sums
__device__ __align__(128) float g_cnt [N_GRAPHS];          // per-graph node counts

__device__ __forceinline__ float* buf_ptr(int sel) {
    return (sel == 1) ? g_bufA : g_bufB;
}

// ---------------- 1. init: deg=1 (self loop), pool=0, cnt=0 ----------------
__global__ void init_kernel() {
    int i = blockIdx.x * blockDim.x + threadIdx.x;
    if (i < N_NODES) g_dis[i] = 1.0f;
    if (i < N_GRAPHS * HID) g_pool[i] = 0.0f;
    if (i < N_GRAPHS) g_cnt[i] = 0.0f;
}

// ---------------- 2. degree accumulation over targets ----------------
__global__ void deg_kernel(const int* __restrict__ col) {
    int e = blockIdx.x * blockDim.x + threadIdx.x;
    if (e < N_EDGES) atomicAdd(&g_dis[col[e]], 1.0f);
}

// ---------------- 3. deg -> rsqrt(deg) ----------------
__global__ void rsqrt_kernel() {
    int i = blockIdx.x * blockDim.x + threadIdx.x;
    if (i < N_NODES) g_dis[i] = rsqrtf(g_dis[i]);
}

// ---------------- 4. GEMM: tmp = act(in) @ W ; out = b + tmp * dis^2 ----------------
// block = 192 threads, 32 rows/block. Thread = (col-group cg of 4 cols, row-slot rs of 4 rows).
#define GEMM_TB 192
#define GEMM_RB 32
__global__ __launch_bounds__(GEMM_TB) void gemm_kernel(
    const float* __restrict__ xin, int in_sel,
    const float* __restrict__ W, const float* __restrict__ b,
    int relu_in, int out_sel)
{
    __shared__ float Ws[HID * HID];        // 36 KB
    __shared__ float hs[GEMM_RB * HID];    // 12 KB
    const float* in  = (in_sel == 0) ? xin : buf_ptr(in_sel);
    float*       out = buf_ptr(out_sel);
    float*       tmp = g_tmp;

    const int tid = threadIdx.x;
    const int r0  = blockIdx.x * GEMM_RB;

    for (int i = tid; i < HID * HID; i += GEMM_TB) Ws[i] = W[i];
    for (int i = tid; i < GEMM_RB * HID; i += GEMM_TB) {
        int r = r0 + i / HID;
        float v = (r < N_NODES) ? in[r * HID + (i % HID)] : 0.0f;
        if (relu_in) v = fmaxf(v, 0.0f);
        hs[i] = v;
    }
    __syncthreads();

    const int cg = tid % 24;   // columns [4*cg, 4*cg+4)
    const int rs = tid / 24;   // rows    [r0 + 4*rs, r0 + 4*rs + 4)

    float acc[4][4];
    #pragma unroll
    for (int j = 0; j < 4; j++)
        #pragma unroll
        for (int c = 0; c < 4; c++) acc[j][c] = 0.0f;

    const float4* W4 = (const float4*)Ws;
    #pragma unroll 4
    for (int k = 0; k < HID; k++) {
        float4 w = W4[k * 24 + cg];
        #pragma unroll
        for (int j = 0; j < 4; j++) {
            float hv = hs[(rs * 4 + j) * HID + k];
            acc[j][0] = fmaf(hv, w.x, acc[j][0]);
            acc[j][1] = fmaf(hv, w.y, acc[j][1]);
            acc[j][2] = fmaf(hv, w.z, acc[j][2]);
            acc[j][3] = fmaf(hv, w.w, acc[j][3]);
        }
    }

    float4 bb = ((const float4*)b)[cg];
    #pragma unroll
    for (int j = 0; j < 4; j++) {
        int r = r0 + rs * 4 + j;
        if (r < N_NODES) {
            float d  = g_dis[r];
            float sn = d * d;                  // self-loop norm = 1/deg
            float4 t = make_float4(acc[j][0], acc[j][1], acc[j][2], acc[j][3]);
            ((float4*)tmp)[r * 24 + cg] = t;
            float4 o = make_float4(bb.x + t.x * sn, bb.y + t.y * sn,
                                   bb.z + t.z * sn, bb.w + t.w * sn);
            ((float4*)out)[r * 24 + cg] = o;
        }
    }
}

// ---------------- 5. edge scatter: out[col] += tmp[row] * dis[row]*dis[col] ----------------
// one warp per edge; lanes 0..23 each move one float4 (16B), 4 scalar atomics each.
__global__ __launch_bounds__(256) void scatter_kernel(
    const int* __restrict__ row, const int* __restrict__ col, int out_sel)
{
    float* out = buf_ptr(out_sel);
    int warp = (blockIdx.x * blockDim.x + threadIdx.x) >> 5;
    int lane = threadIdx.x & 31;
    if (warp >= N_EDGES) return;
    int r = row[warp];
    int c = col[warp];
    float nrm = g_dis[r] * g_dis[c];
    if (lane < 24) {
        float4 v = ((const float4*)g_tmp)[r * 24 + lane];
        float* dst = out + c * HID + lane * 4;
        atomicAdd(dst + 0, v.x * nrm);
        atomicAdd(dst + 1, v.y * nrm);
        atomicAdd(dst + 2, v.z * nrm);
        atomicAdd(dst + 3, v.w * nrm);
    }
}

// ---------------- 6. mean-pool accumulation (relu fused) ----------------
__global__ __launch_bounds__(256) void pool_kernel(const int* __restrict__ batch)
{
    int warp = (blockIdx.x * blockDim.x + threadIdx.x) >> 5;
    int lane = threadIdx.x & 31;
    if (warp >= N_NODES) return;
    int g = batch[warp];
    if (lane < 24) {
        float4 v = ((const float4*)g_bufA)[warp * 24 + lane];
        float* dst = g_pool + g * HID + lane * 4;
        atomicAdd(dst + 0, fmaxf(v.x, 0.0f));
        atomicAdd(dst + 1, fmaxf(v.y, 0.0f));
        atomicAdd(dst + 2, fmaxf(v.z, 0.0f));
        atomicAdd(dst + 3, fmaxf(v.w, 0.0f));
    } else if (lane == 24) {
        atomicAdd(&g_cnt[g], 1.0f);
    }
}

// ---------------- 7. final: out = (pool / max(cnt,1)) @ fc_w + fc_b ----------------
__global__ __launch_bounds__(256) void final_kernel(
    const float* __restrict__ fc_w, const float* __restrict__ fc_b,
    float* __restrict__ out)
{
    int t = blockIdx.x * blockDim.x + threadIdx.x;   // 8192 = 256 graphs x 32 outs
    if (t >= N_GRAPHS * OUT_DIM) return;
    int g = t >> 5;
    int o = t & 31;
    float inv = 1.0f / fmaxf(g_cnt[g], 1.0f);
    float acc = fc_b[o];
    #pragma unroll 8
    for (int f = 0; f < HID; f++)
        acc = fmaf(g_pool[g * HID + f] * inv, fc_w[f * OUT_DIM + o], acc);
    out[t] = acc;
}

// ---------------- launch ----------------
extern "C" void kernel_launch(void* const* d_in, const int* in_sizes, int n_in,
                              void* d_out, int out_size)
{
    const float* x    = (const float*)d_in[0];
    const int*   ei   = (const int*)d_in[1];   // [2, E] int32 (JAX x64 disabled)
    const int*   bat  = (const int*)d_in[2];   // [N] int32
    const float* W1   = (const float*)d_in[3];
    const float* b1   = (const float*)d_in[4];
    const float* W2   = (const float*)d_in[5];
    const float* b2   = (const float*)d_in[6];
    const float* W3   = (const float*)d_in[7];
    const float* b3   = (const float*)d_in[8];
    const float* fc_w = (const float*)d_in[9];
    const float* fc_b = (const float*)d_in[10];
    float* out = (float*)d_out;

    const int* erow = ei;
    const int* ecol = ei + N_EDGES;

    // degree / normalization
    init_kernel<<<(N_NODES + 255) / 256, 256>>>();
    deg_kernel<<<(N_EDGES + 255) / 256, 256>>>(ecol);
    rsqrt_kernel<<<(N_NODES + 255) / 256, 256>>>();

    const int gemm_grid    = (N_NODES + GEMM_RB - 1) / GEMM_RB;
    const int scatter_grid = (N_EDGES * 32 + 255) / 256;
    const int pool_grid    = (N_NODES * 32 + 255) / 256;

    // layer 1: x -> bufA (sel 1)
    gemm_kernel<<<gemm_grid, GEMM_TB>>>(x, 0, W1, b1, 0, 1);
    scatter_kernel<<<scatter_grid, 256>>>(erow, ecol, 1);
    // layer 2: relu(bufA) -> bufB (sel 2)
    gemm_kernel<<<gemm_grid, GEMM_TB>>>(nullptr, 1, W2, b2, 1, 2);
    scatter_kernel<<<scatter_grid, 256>>>(erow, ecol, 2);
    // layer 3: relu(bufB) -> bufA (sel 1)
    gemm_kernel<<<gemm_grid, GEMM_TB>>>(nullptr, 2, W3, b3, 1, 1);
    scatter_kernel<<<scatter_grid, 256>>>(erow, ecol, 1);

    // mean pool (relu fused) + FC
    pool_kernel<<<pool_grid, 256>>>(bat);
    final_kernel<<<(N_GRAPHS * OUT_DIM + 255) / 256, 256>>>(fc_w, fc_b, out);
}

// round 4
// speedup vs baseline: 2.0684x; 2.0684x over previous
#include <cuda_runtime.h>
#include <cuda_bf16.h>
#include <cstdint>

#define N_NODES  50000
#define N_EDGES  800000
#define HID      96
#define OUT_DIM  32
#define N_GRAPHS 256

// ---------------- scratch (static device globals; no allocation) ----------------
__device__ __align__(128) float g_dis[N_NODES];            // d^{-1/2}
__device__ __align__(128) float g_tmp [N_NODES * HID];     // (h @ W) * dis[r]
__device__ __align__(128) float g_bufA[N_NODES * HID];     // layer outputs (ping)
__device__ __align__(128) float g_bufB[N_NODES * HID];     // layer outputs (pong)
__device__ __align__(128) float g_pool[N_GRAPHS * HID];    // per-graph feature sums
__device__ __align__(128) float g_cnt [N_GRAPHS];          // per-graph node counts
// CSR (edges grouped by target/col)
__device__ __align__(128) int g_cntin [N_NODES];           // incoming-edge counts
__device__ __align__(128) int g_rowptr[N_NODES + 1];
__device__ __align__(128) int g_cursor[N_NODES];
__device__ __align__(128) int g_srcs  [N_EDGES];           // source node per CSR slot

__device__ __forceinline__ float* buf_ptr(int sel) {
    return (sel == 1) ? g_bufA : g_bufB;
}

// ---------------- 1. zero counters ----------------
__global__ void zero_kernel() {
    int i = blockIdx.x * blockDim.x + threadIdx.x;
    if (i < N_NODES) g_cntin[i] = 0;
    if (i < N_GRAPHS * HID) g_pool[i] = 0.0f;
    if (i < N_GRAPHS) g_cnt[i] = 0.0f;
}

// ---------------- 2. histogram of targets ----------------
__global__ void hist_kernel(const int* __restrict__ col) {
    int e = blockIdx.x * blockDim.x + threadIdx.x;
    if (e < N_EDGES) atomicAdd(&g_cntin[col[e]], 1);
}

// ---------------- 3. single-block exclusive scan + dis = rsqrt(1+cnt) ----------------
__global__ __launch_bounds__(1024) void scan_kernel() {
    __shared__ int warp_sums[32];
    __shared__ int carry_s;
    const int tid  = threadIdx.x;
    const int lane = tid & 31;
    const int wid  = tid >> 5;
    if (tid == 0) carry_s = 0;
    __syncthreads();

    for (int base = 0; base < N_NODES; base += 1024) {
        int i = base + tid;
        int v = (i < N_NODES) ? g_cntin[i] : 0;
        // inclusive warp scan
        int x = v;
        #pragma unroll
        for (int o = 1; o < 32; o <<= 1) {
            int y = __shfl_up_sync(0xFFFFFFFFu, x, o);
            if (lane >= o) x += y;
        }
        if (lane == 31) warp_sums[wid] = x;
        __syncthreads();
        if (wid == 0) {
            int s = warp_sums[lane];
            #pragma unroll
            for (int o = 1; o < 32; o <<= 1) {
                int y = __shfl_up_sync(0xFFFFFFFFu, s, o);
                if (lane >= o) s += y;
            }
            warp_sums[lane] = s;
        }
        __syncthreads();
        int warp_off = (wid == 0) ? 0 : warp_sums[wid - 1];
        int excl = carry_s + warp_off + x - v;
        if (i < N_NODES) {
            g_rowptr[i] = excl;
            g_cursor[i] = excl;
            g_dis[i]    = rsqrtf(1.0f + (float)v);   // deg = self-loop + incoming
        }
        __syncthreads();
        if (tid == 0) carry_s += warp_sums[31];
        __syncthreads();
    }
    if (tid == 0) g_rowptr[N_NODES] = carry_s;
}

// ---------------- 4. fill CSR slots ----------------
__global__ void fill_kernel(const int* __restrict__ row, const int* __restrict__ col) {
    int e = blockIdx.x * blockDim.x + threadIdx.x;
    if (e >= N_EDGES) return;
    int p = atomicAdd(&g_cursor[col[e]], 1);
    g_srcs[p] = row[e];
}

// ---------------- 5. GEMM: tmp2 = act(in) @ W * dis[r] ----------------
#define GEMM_TB 192
#define GEMM_RB 32
__global__ __launch_bounds__(GEMM_TB) void gemm_kernel(
    const float* __restrict__ xin, int in_sel,
    const float* __restrict__ W, int relu_in)
{
    __shared__ float Ws[HID * HID];        // 36 KB
    __shared__ float hs[GEMM_RB * HID];    // 12 KB
    const float* in = (in_sel == 0) ? xin : buf_ptr(in_sel);
    float* tmp = g_tmp;

    const int tid = threadIdx.x;
    const int r0  = blockIdx.x * GEMM_RB;

    for (int i = tid; i < HID * HID; i += GEMM_TB) Ws[i] = W[i];
    for (int i = tid; i < GEMM_RB * HID; i += GEMM_TB) {
        int r = r0 + i / HID;
        float v = (r < N_NODES) ? in[r * HID + (i % HID)] : 0.0f;
        if (relu_in) v = fmaxf(v, 0.0f);
        hs[i] = v;
    }
    __syncthreads();

    const int cg = tid % 24;   // columns [4*cg, 4*cg+4)
    const int rs = tid / 24;   // rows    [r0 + 4*rs, r0 + 4*rs + 4)

    float acc[4][4];
    #pragma unroll
    for (int j = 0; j < 4; j++)
        #pragma unroll
        for (int c = 0; c < 4; c++) acc[j][c] = 0.0f;

    const float4* W4 = (const float4*)Ws;
    #pragma unroll 4
    for (int k = 0; k < HID; k++) {
        float4 w = W4[k * 24 + cg];
        #pragma unroll
        for (int j = 0; j < 4; j++) {
            float hv = hs[(rs * 4 + j) * HID + k];
            acc[j][0] = fmaf(hv, w.x, acc[j][0]);
            acc[j][1] = fmaf(hv, w.y, acc[j][1]);
            acc[j][2] = fmaf(hv, w.z, acc[j][2]);
            acc[j][3] = fmaf(hv, w.w, acc[j][3]);
        }
    }

    #pragma unroll
    for (int j = 0; j < 4; j++) {
        int r = r0 + rs * 4 + j;
        if (r < N_NODES) {
            float d = g_dis[r];
            ((float4*)tmp)[r * 24 + cg] =
                make_float4(acc[j][0] * d, acc[j][1] * d, acc[j][2] * d, acc[j][3] * d);
        }
    }
}

// ---------------- 6. gather: out[c] = b + dis[c] * (tmp2[c] + sum_in tmp2[src]) ----------------
__global__ __launch_bounds__(256) void gather_kernel(
    const float* __restrict__ b, int out_sel)
{
    float* out = buf_ptr(out_sel);
    int c    = (blockIdx.x * blockDim.x + threadIdx.x) >> 5;
    int lane = threadIdx.x & 31;
    if (c >= N_NODES || lane >= 24) return;

    int beg = g_rowptr[c];
    int end = g_rowptr[c + 1];

    float4 acc  = ((const float4*)g_tmp)[c * 24 + lane];   // self term
    float4 acc2 = make_float4(0.f, 0.f, 0.f, 0.f);

    int e = beg;
    for (; e + 1 < end; e += 2) {
        int r0 = __ldg(&g_srcs[e]);
        int r1 = __ldg(&g_srcs[e + 1]);
        float4 v0 = ((const float4*)g_tmp)[r0 * 24 + lane];
        float4 v1 = ((const float4*)g_tmp)[r1 * 24 + lane];
        acc.x  += v0.x; acc.y  += v0.y; acc.z  += v0.z; acc.w  += v0.w;
        acc2.x += v1.x; acc2.y += v1.y; acc2.z += v1.z; acc2.w += v1.w;
    }
    if (e < end) {
        int r0 = __ldg(&g_srcs[e]);
        float4 v0 = ((const float4*)g_tmp)[r0 * 24 + lane];
        acc.x += v0.x; acc.y += v0.y; acc.z += v0.z; acc.w += v0.w;
    }
    acc.x += acc2.x; acc.y += acc2.y; acc.z += acc2.z; acc.w += acc2.w;

    float  d  = g_dis[c];
    float4 bb = ((const float4*)b)[lane];
    ((float4*)out)[c * 24 + lane] =
        make_float4(bb.x + d * acc.x, bb.y + d * acc.y,
                    bb.z + d * acc.z, bb.w + d * acc.w);
}

// ---------------- 7. mean-pool accumulation (relu fused) ----------------
__global__ __launch_bounds__(256) void pool_kernel(const int* __restrict__ batch)
{
    int n    = (blockIdx.x * blockDim.x + threadIdx.x) >> 5;
    int lane = threadIdx.x & 31;
    if (n >= N_NODES) return;
    int g = batch[n];
    if (lane < 24) {
        float4 v = ((const float4*)g_bufA)[n * 24 + lane];
        float* dst = g_pool + g * HID + lane * 4;
        atomicAdd(dst + 0, fmaxf(v.x, 0.0f));
        atomicAdd(dst + 1, fmaxf(v.y, 0.0f));
        atomicAdd(dst + 2, fmaxf(v.z, 0.0f));
        atomicAdd(dst + 3, fmaxf(v.w, 0.0f));
    } else if (lane == 24) {
        atomicAdd(&g_cnt[g], 1.0f);
    }
}

// ---------------- 8. final: out = (pool / max(cnt,1)) @ fc_w + fc_b ----------------
__global__ __launch_bounds__(256) void final_kernel(
    const float* __restrict__ fc_w, const float* __restrict__ fc_b,
    float* __restrict__ out)
{
    int t = blockIdx.x * blockDim.x + threadIdx.x;   // 8192
    if (t >= N_GRAPHS * OUT_DIM) return;
    int g = t >> 5;
    int o = t & 31;
    float inv = 1.0f / fmaxf(g_cnt[g], 1.0f);
    float acc = fc_b[o];
    #pragma unroll 8
    for (int f = 0; f < HID; f++)
        acc = fmaf(g_pool[g * HID + f] * inv, fc_w[f * OUT_DIM + o], acc);
    out[t] = acc;
}

// ---------------- launch ----------------
extern "C" void kernel_launch(void* const* d_in, const int* in_sizes, int n_in,
                              void* d_out, int out_size)
{
    const float* x    = (const float*)d_in[0];
    const int*   ei   = (const int*)d_in[1];   // [2, E] int32
    const int*   bat  = (const int*)d_in[2];   // [N] int32
    const float* W1   = (const float*)d_in[3];
    const float* b1   = (const float*)d_in[4];
    const float* W2   = (const float*)d_in[5];
    const float* b2   = (const float*)d_in[6];
    const float* W3   = (const float*)d_in[7];
    const float* b3   = (const float*)d_in[8];
    const float* fc_w = (const float*)d_in[9];
    const float* fc_b = (const float*)d_in[10];
    float* out = (float*)d_out;

    const int* erow = ei;
    const int* ecol = ei + N_EDGES;

    // CSR build + normalization
    zero_kernel<<<(N_NODES + 255) / 256, 256>>>();
    hist_kernel<<<(N_EDGES + 255) / 256, 256>>>(ecol);
    scan_kernel<<<1, 1024>>>();
    fill_kernel<<<(N_EDGES + 255) / 256, 256>>>(erow, ecol);

    const int gemm_grid   = (N_NODES + GEMM_RB - 1) / GEMM_RB;
    const int node_warps  = (N_NODES * 32 + 255) / 256;

    // layer 1: x -> bufA
    gemm_kernel<<<gemm_grid, GEMM_TB>>>(x, 0, W1, 0);
    gather_kernel<<<node_warps, 256>>>(b1, 1);
    // layer 2: relu(bufA) -> bufB
    gemm_kernel<<<gemm_grid, GEMM_TB>>>(nullptr, 1, W2, 1);
    gather_kernel<<<node_warps, 256>>>(b2, 2);
    // layer 3: relu(bufB) -> bufA
    gemm_kernel<<<gemm_grid, GEMM_TB>>>(nullptr, 2, W3, 1);
    gather_kernel<<<node_warps, 256>>>(b3, 1);

    // mean pool (relu fused) + FC
    pool_kernel<<<node_warps, 256>>>(bat);
    final_kernel<<<(N_GRAPHS * OUT_DIM + 255) / 256, 256>>>(fc_w, fc_b, out);
}

// round 5
// speedup vs baseline: 2.6316x; 1.2723x over previous
#include <cuda_runtime.h>
#include <cuda_bf16.h>
#include <cstdint>

#define N_NODES  50000
#define N_EDGES  800000
#define HID      96
#define OUT_DIM  32
#define N_GRAPHS 256

// ---------------- scratch (static device globals; no allocation) ----------------
__device__ __align__(128) float g_dis[N_NODES];            // d^{-1/2}
__device__ __align__(128) float g_tmp [N_NODES * HID];     // (h @ W) * dis[r]
__device__ __align__(128) float g_bufA[N_NODES * HID];     // layer outputs (ping)
__device__ __align__(128) float g_bufB[N_NODES * HID];     // layer outputs (pong)
__device__ __align__(128) float g_pool[N_GRAPHS * HID];    // per-graph feature sums
__device__ __align__(128) float g_cnt [N_GRAPHS];          // per-graph node counts
// CSR (edges grouped by target/col)
__device__ __align__(128) int g_cntin [N_NODES];           // incoming-edge counts
__device__ __align__(128) int g_rowptr[N_NODES + 1];
__device__ __align__(128) int g_cursor[N_NODES];
__device__ __align__(128) int g_srcs  [N_EDGES];           // source node per CSR slot

__device__ __forceinline__ float* buf_ptr(int sel) {
    return (sel == 1) ? g_bufA : g_bufB;
}

// ---------------- 1. zero counters ----------------
__global__ void zero_kernel() {
    int i = blockIdx.x * blockDim.x + threadIdx.x;
    if (i < N_NODES) g_cntin[i] = 0;
    if (i < N_GRAPHS * HID) g_pool[i] = 0.0f;
    if (i < N_GRAPHS) g_cnt[i] = 0.0f;
}

// ---------------- 2. histogram of targets ----------------
__global__ void hist_kernel(const int* __restrict__ col) {
    int e = blockIdx.x * blockDim.x + threadIdx.x;
    if (e < N_EDGES) atomicAdd(&g_cntin[col[e]], 1);
}

// ---------------- 3. single-block exclusive scan (int4-vectorized) ----------------
// Also writes cursor copy and dis = rsqrt(1 + in_count). N_NODES % 4 == 0.
__global__ __launch_bounds__(1024) void scan_kernel() {
    __shared__ int warp_sums[32];
    __shared__ int carry_s;
    const int tid  = threadIdx.x;
    const int lane = tid & 31;
    const int wid  = tid >> 5;
    if (tid == 0) carry_s = 0;
    __syncthreads();

    const int NV4 = N_NODES / 4;   // 12500
    for (int base = 0; base < NV4; base += 1024) {
        int i4 = base + tid;
        int4 v = make_int4(0, 0, 0, 0);
        if (i4 < NV4) v = ((const int4*)g_cntin)[i4];
        int t = v.x + v.y + v.z + v.w;
        int x = t;
        #pragma unroll
        for (int o = 1; o < 32; o <<= 1) {
            int y = __shfl_up_sync(0xFFFFFFFFu, x, o);
            if (lane >= o) x += y;
        }
        if (lane == 31) warp_sums[wid] = x;
        __syncthreads();
        if (wid == 0) {
            int s = warp_sums[lane];
            #pragma unroll
            for (int o = 1; o < 32; o <<= 1) {
                int y = __shfl_up_sync(0xFFFFFFFFu, s, o);
                if (lane >= o) s += y;
            }
            warp_sums[lane] = s;
        }
        __syncthreads();
        int excl = carry_s + ((wid == 0) ? 0 : warp_sums[wid - 1]) + x - t;
        if (i4 < NV4) {
            int i  = i4 * 4;
            int e0 = excl, e1 = e0 + v.x, e2 = e1 + v.y, e3 = e2 + v.z;
            ((int4*)g_rowptr)[i4] = make_int4(e0, e1, e2, e3);
            ((int4*)g_cursor)[i4] = make_int4(e0, e1, e2, e3);
            ((float4*)g_dis)[i4]  = make_float4(rsqrtf(1.0f + (float)v.x),
                                                rsqrtf(1.0f + (float)v.y),
                                                rsqrtf(1.0f + (float)v.z),
                                                rsqrtf(1.0f + (float)v.w));
        }
        __syncthreads();
        if (tid == 0) carry_s += warp_sums[31];
        __syncthreads();
    }
    if (tid == 0) g_rowptr[N_NODES] = carry_s;
}

// ---------------- 4. fill CSR slots ----------------
__global__ void fill_kernel(const int* __restrict__ row, const int* __restrict__ col) {
    int e = blockIdx.x * blockDim.x + threadIdx.x;
    if (e >= N_EDGES) return;
    int p = atomicAdd(&g_cursor[col[e]], 1);
    g_srcs[p] = row[e];
}

// ---------------- 5. GEMM: tmp2 = act(in) @ W * dis[r] ----------------
// 384 threads, 64 rows/block, 60 KB dynamic smem -> 3 blocks/SM (56% occ).
// Thread = (cg: 4 cols, rs: 4 rows). Per k: 1 LDS.128 (W) + 4 bcast LDS (h) + 16 FFMA.
#define GEMM_TB 384
#define GEMM_RB 64
#define GEMM_SMEM ((HID * HID + GEMM_RB * HID) * 4)   // 61440 B
__global__ __launch_bounds__(GEMM_TB, 3) void gemm_kernel(
    const float* __restrict__ xin, int in_sel,
    const float* __restrict__ W, int relu_in)
{
    extern __shared__ float smem[];
    float* Ws = smem;                 // HID*HID
    float* hs = smem + HID * HID;     // GEMM_RB*HID
    const float* in = (in_sel == 0) ? xin : buf_ptr(in_sel);
    float* tmp = g_tmp;

    const int tid = threadIdx.x;
    const int r0  = blockIdx.x * GEMM_RB;

    // load W (float4): 2304 vec / 384 thr = 6 each
    #pragma unroll
    for (int i4 = tid; i4 < HID * HID / 4; i4 += GEMM_TB)
        ((float4*)Ws)[i4] = ((const float4*)W)[i4];
    // load h tile (float4): 1536 vec / 384 thr = 4 each
    #pragma unroll
    for (int i4 = tid; i4 < GEMM_RB * HID / 4; i4 += GEMM_TB) {
        int r  = i4 / (HID / 4);
        int c4 = i4 % (HID / 4);
        float4 v = make_float4(0.f, 0.f, 0.f, 0.f);
        if (r0 + r < N_NODES) v = ((const float4*)(in + (size_t)(r0 + r) * HID))[c4];
        if (relu_in) {
            v.x = fmaxf(v.x, 0.f); v.y = fmaxf(v.y, 0.f);
            v.z = fmaxf(v.z, 0.f); v.w = fmaxf(v.w, 0.f);
        }
        ((float4*)hs)[i4] = v;
    }
    __syncthreads();

    const int cg = tid % 24;   // columns [4*cg, 4*cg+4)
    const int rs = tid / 24;   // rows    [r0 + 4*rs, r0 + 4*rs + 4)

    float acc[4][4];
    #pragma unroll
    for (int j = 0; j < 4; j++)
        #pragma unroll
        for (int c = 0; c < 4; c++) acc[j][c] = 0.0f;

    const float4* W4 = (const float4*)Ws;
    #pragma unroll 4
    for (int k = 0; k < HID; k++) {
        float4 w = W4[k * 24 + cg];
        #pragma unroll
        for (int j = 0; j < 4; j++) {
            float hv = hs[(rs * 4 + j) * HID + k];
            acc[j][0] = fmaf(hv, w.x, acc[j][0]);
            acc[j][1] = fmaf(hv, w.y, acc[j][1]);
            acc[j][2] = fmaf(hv, w.z, acc[j][2]);
            acc[j][3] = fmaf(hv, w.w, acc[j][3]);
        }
    }

    #pragma unroll
    for (int j = 0; j < 4; j++) {
        int r = r0 + rs * 4 + j;
        if (r < N_NODES) {
            float d = g_dis[r];
            ((float4*)tmp)[r * 24 + cg] =
                make_float4(acc[j][0] * d, acc[j][1] * d, acc[j][2] * d, acc[j][3] * d);
        }
    }
}

// ---------------- 6. gather: out[c] = b + dis[c] * (tmp2[c] + sum_in tmp2[src]) ----------------
__global__ __launch_bounds__(256) void gather_kernel(
    const float* __restrict__ b, int out_sel)
{
    float* out = buf_ptr(out_sel);
    int c    = (blockIdx.x * blockDim.x + threadIdx.x) >> 5;
    int lane = threadIdx.x & 31;
    if (c >= N_NODES || lane >= 24) return;

    int beg = g_rowptr[c];
    int end = g_rowptr[c + 1];

    float4 acc  = ((const float4*)g_tmp)[c * 24 + lane];   // self term
    float4 acc2 = make_float4(0.f, 0.f, 0.f, 0.f);

    int e = beg;
    for (; e + 1 < end; e += 2) {
        int r0 = __ldg(&g_srcs[e]);
        int r1 = __ldg(&g_srcs[e + 1]);
        float4 v0 = ((const float4*)g_tmp)[r0 * 24 + lane];
        float4 v1 = ((const float4*)g_tmp)[r1 * 24 + lane];
        acc.x  += v0.x; acc.y  += v0.y; acc.z  += v0.z; acc.w  += v0.w;
        acc2.x += v1.x; acc2.y += v1.y; acc2.z += v1.z; acc2.w += v1.w;
    }
    if (e < end) {
        int r0 = __ldg(&g_srcs[e]);
        float4 v0 = ((const float4*)g_tmp)[r0 * 24 + lane];
        acc.x += v0.x; acc.y += v0.y; acc.z += v0.z; acc.w += v0.w;
    }
    acc.x += acc2.x; acc.y += acc2.y; acc.z += acc2.z; acc.w += acc2.w;

    float  d  = g_dis[c];
    float4 bb = ((const float4*)b)[lane];
    ((float4*)out)[c * 24 + lane] =
        make_float4(bb.x + d * acc.x, bb.y + d * acc.y,
                    bb.z + d * acc.z, bb.w + d * acc.w);
}

// ---------------- 7. mean-pool accumulation (relu fused) ----------------
__global__ __launch_bounds__(256) void pool_kernel(const int* __restrict__ batch)
{
    int n    = (blockIdx.x * blockDim.x + threadIdx.x) >> 5;
    int lane = threadIdx.x & 31;
    if (n >= N_NODES) return;
    int g = batch[n];
    if (lane < 24) {
        float4 v = ((const float4*)g_bufA)[n * 24 + lane];
        float* dst = g_pool + g * HID + lane * 4;
        atomicAdd(dst + 0, fmaxf(v.x, 0.0f));
        atomicAdd(dst + 1, fmaxf(v.y, 0.0f));
        atomicAdd(dst + 2, fmaxf(v.z, 0.0f));
        atomicAdd(dst + 3, fmaxf(v.w, 0.0f));
    } else if (lane == 24) {
        atomicAdd(&g_cnt[g], 1.0f);
    }
}

// ---------------- 8. final: out = (pool / max(cnt,1)) @ fc_w + fc_b ----------------
__global__ __launch_bounds__(256) void final_kernel(
    const float* __restrict__ fc_w, const float* __restrict__ fc_b,
    float* __restrict__ out)
{
    int t = blockIdx.x * blockDim.x + threadIdx.x;   // 8192
    if (t >= N_GRAPHS * OUT_DIM) return;
    int g = t >> 5;
    int o = t & 31;
    float inv = 1.0f / fmaxf(g_cnt[g], 1.0f);
    float acc = fc_b[o];
    #pragma unroll 8
    for (int f = 0; f < HID; f++)
        acc = fmaf(g_pool[g * HID + f] * inv, fc_w[f * OUT_DIM + o], acc);
    out[t] = acc;
}

// ---------------- launch ----------------
extern "C" void kernel_launch(void* const* d_in, const int* in_sizes, int n_in,
                              void* d_out, int out_size)
{
    const float* x    = (const float*)d_in[0];
    const int*   ei   = (const int*)d_in[1];   // [2, E] int32
    const int*   bat  = (const int*)d_in[2];   // [N] int32
    const float* W1   = (const float*)d_in[3];
    const float* b1   = (const float*)d_in[4];
    const float* W2   = (const float*)d_in[5];
    const float* b2   = (const float*)d_in[6];
    const float* W3   = (const float*)d_in[7];
    const float* b3   = (const float*)d_in[8];
    const float* fc_w = (const float*)d_in[9];
    const float* fc_b = (const float*)d_in[10];
    float* out = (float*)d_out;

    const int* erow = ei;
    const int* ecol = ei + N_EDGES;

    static bool attr_set = false;
    if (!attr_set) {
        cudaFuncSetAttribute(gemm_kernel,
                             cudaFuncAttributeMaxDynamicSharedMemorySize, GEMM_SMEM);
        attr_set = true;
    }

    // CSR build + normalization
    zero_kernel<<<(N_NODES + 255) / 256, 256>>>();
    hist_kernel<<<(N_EDGES + 255) / 256, 256>>>(ecol);
    scan_kernel<<<1, 1024>>>();
    fill_kernel<<<(N_EDGES + 255) / 256, 256>>>(erow, ecol);

    const int gemm_grid   = (N_NODES + GEMM_RB - 1) / GEMM_RB;
    const int node_warps  = (N_NODES * 32 + 255) / 256;

    // layer 1: x -> bufA
    gemm_kernel<<<gemm_grid, GEMM_TB, GEMM_SMEM>>>(x, 0, W1, 0);
    gather_kernel<<<node_warps, 256>>>(b1, 1);
    // layer 2: relu(bufA) -> bufB
    gemm_kernel<<<gemm_grid, GEMM_TB, GEMM_SMEM>>>(nullptr, 1, W2, 1);
    gather_kernel<<<node_warps, 256>>>(b2, 2);
    // layer 3: relu(bufB) -> bufA
    gemm_kernel<<<gemm_grid, GEMM_TB, GEMM_SMEM>>>(nullptr, 2, W3, 1);
    gather_kernel<<<node_warps, 256>>>(b3, 1);

    // mean pool (relu fused) + FC
    pool_kernel<<<node_warps, 256>>>(bat);
    final_kernel<<<(N_GRAPHS * OUT_DIM + 255) / 256, 256>>>(fc_w, fc_b, out);
}

// round 6
// speedup vs baseline: 3.1647x; 1.2026x over previous
#include <cuda_runtime.h>
#include <cuda_bf16.h>
#include <cstdint>

#define N_NODES  50000
#define N_EDGES  800000
#define HID      96
#define OUT_DIM  32
#define N_GRAPHS 256

// ---------------- scratch (static device globals; no allocation) ----------------
__device__ __align__(128) float g_dis[N_NODES];            // d^{-1/2}
__device__ __align__(128) float g_tmp [N_NODES * HID];     // (h @ W) * dis[r]
__device__ __align__(128) float g_bufA[N_NODES * HID];     // layer outputs (ping)
__device__ __align__(128) float g_bufB[N_NODES * HID];     // layer outputs (pong)
__device__ __align__(128) float g_pool[N_GRAPHS * HID];    // per-graph feature sums
__device__ __align__(128) float g_cnt [N_GRAPHS];          // per-graph node counts
// CSR (edges grouped by target/col)
__device__ __align__(128) int g_cntin [N_NODES];
__device__ __align__(128) int g_rowptr[N_NODES + 1];
__device__ __align__(128) int g_cursor[N_NODES];
__device__ __align__(128) int g_srcs  [N_EDGES];

__device__ __forceinline__ float* buf_ptr(int sel) {
    return (sel == 1) ? g_bufA : g_bufB;
}

__device__ __forceinline__ float to_tf32(float x) {
    uint32_t r;
    asm("cvt.rna.tf32.f32 %0, %1;" : "=r"(r) : "f"(x));
    return __uint_as_float(r);
}

// ---------------- 1. zero counters ----------------
__global__ void zero_kernel() {
    int i = blockIdx.x * blockDim.x + threadIdx.x;
    if (i < N_NODES) g_cntin[i] = 0;
    if (i < N_GRAPHS * HID) g_pool[i] = 0.0f;
    if (i < N_GRAPHS) g_cnt[i] = 0.0f;
}

// ---------------- 2. histogram of targets ----------------
__global__ void hist_kernel(const int* __restrict__ col) {
    int e = blockIdx.x * blockDim.x + threadIdx.x;
    if (e < N_EDGES) atomicAdd(&g_cntin[col[e]], 1);
}

// ---------------- 3. single-block exclusive scan (int4-vectorized) ----------------
__global__ __launch_bounds__(1024) void scan_kernel() {
    __shared__ int warp_sums[32];
    __shared__ int carry_s;
    const int tid  = threadIdx.x;
    const int lane = tid & 31;
    const int wid  = tid >> 5;
    if (tid == 0) carry_s = 0;
    __syncthreads();

    const int NV4 = N_NODES / 4;   // 12500
    for (int base = 0; base < NV4; base += 1024) {
        int i4 = base + tid;
        int4 v = make_int4(0, 0, 0, 0);
        if (i4 < NV4) v = ((const int4*)g_cntin)[i4];
        int t = v.x + v.y + v.z + v.w;
        int x = t;
        #pragma unroll
        for (int o = 1; o < 32; o <<= 1) {
            int y = __shfl_up_sync(0xFFFFFFFFu, x, o);
            if (lane >= o) x += y;
        }
        if (lane == 31) warp_sums[wid] = x;
        __syncthreads();
        if (wid == 0) {
            int s = warp_sums[lane];
            #pragma unroll
            for (int o = 1; o < 32; o <<= 1) {
                int y = __shfl_up_sync(0xFFFFFFFFu, s, o);
                if (lane >= o) s += y;
            }
            warp_sums[lane] = s;
        }
        __syncthreads();
        int excl = carry_s + ((wid == 0) ? 0 : warp_sums[wid - 1]) + x - t;
        if (i4 < NV4) {
            int e0 = excl, e1 = e0 + v.x, e2 = e1 + v.y, e3 = e2 + v.z;
            ((int4*)g_rowptr)[i4] = make_int4(e0, e1, e2, e3);
            ((int4*)g_cursor)[i4] = make_int4(e0, e1, e2, e3);
            ((float4*)g_dis)[i4]  = make_float4(rsqrtf(1.0f + (float)v.x),
                                                rsqrtf(1.0f + (float)v.y),
                                                rsqrtf(1.0f + (float)v.z),
                                                rsqrtf(1.0f + (float)v.w));
        }
        __syncthreads();
        if (tid == 0) carry_s += warp_sums[31];
        __syncthreads();
    }
    if (tid == 0) g_rowptr[N_NODES] = carry_s;
}

// ---------------- 4. fill CSR slots ----------------
__global__ void fill_kernel(const int* __restrict__ row, const int* __restrict__ col) {
    int e = blockIdx.x * blockDim.x + threadIdx.x;
    if (e >= N_EDGES) return;
    int p = atomicAdd(&g_cursor[col[e]], 1);
    g_srcs[p] = row[e];
}

// ---------------- 5. tf32 MMA GEMM: tmp = (act(in) @ W) * dis[r] ----------------
// 256 threads = 8 warps, 128 rows/block (16 rows/warp). m16n8k8 tf32 mma.
// smem stride 104: B-frag LDS conflict-free, A-frag worst 2-way.
#define GMT 256
#define GMR 128
#define SST 104                                       // smem row stride (floats)
#define GEMM_SMEM ((HID + GMR) * SST * 4)             // (96+128)*104*4 = 93184 B
__global__ __launch_bounds__(GMT) void gemm_kernel(
    const float* __restrict__ xin, int in_sel,
    const float* __restrict__ W, int relu_in)
{
    extern __shared__ float smem[];
    float* Ws = smem;              // [96][104]
    float* hs = smem + HID * SST;  // [128][104]
    const float* in = (in_sel == 0) ? xin : buf_ptr(in_sel);

    const int tid = threadIdx.x;
    const int r0  = blockIdx.x * GMR;

    // stage W (tf32-rounded)
    #pragma unroll
    for (int i4 = tid; i4 < HID * (HID / 4); i4 += GMT) {
        int r = i4 / (HID / 4), c4 = i4 % (HID / 4);
        float4 v = ((const float4*)W)[i4];
        float* d = Ws + r * SST + c4 * 4;
        d[0] = to_tf32(v.x); d[1] = to_tf32(v.y);
        d[2] = to_tf32(v.z); d[3] = to_tf32(v.w);
    }
    // stage h tile (relu + tf32-rounded)
    #pragma unroll
    for (int i4 = tid; i4 < GMR * (HID / 4); i4 += GMT) {
        int r = i4 / (HID / 4), c4 = i4 % (HID / 4);
        float4 v = make_float4(0.f, 0.f, 0.f, 0.f);
        if (r0 + r < N_NODES) v = ((const float4*)(in + (size_t)(r0 + r) * HID))[c4];
        if (relu_in) {
            v.x = fmaxf(v.x, 0.f); v.y = fmaxf(v.y, 0.f);
            v.z = fmaxf(v.z, 0.f); v.w = fmaxf(v.w, 0.f);
        }
        float* d = hs + r * SST + c4 * 4;
        d[0] = to_tf32(v.x); d[1] = to_tf32(v.y);
        d[2] = to_tf32(v.z); d[3] = to_tf32(v.w);
    }
    __syncthreads();

    const int warp = tid >> 5;
    const int lane = tid & 31;
    const int gID  = lane >> 2;   // group id 0..7
    const int tig  = lane & 3;    // thread in group 0..3
    const int wm   = warp * 16;   // warp's row offset in tile

    float c[12][4];
    #pragma unroll
    for (int j = 0; j < 12; j++)
        #pragma unroll
        for (int q = 0; q < 4; q++) c[j][q] = 0.0f;

    #pragma unroll
    for (int k0 = 0; k0 < HID; k0 += 8) {
        const float* ha = hs + (wm + gID) * SST + k0 + tig;
        uint32_t a0 = __float_as_uint(ha[0]);
        uint32_t a1 = __float_as_uint(ha[8 * SST]);
        uint32_t a2 = __float_as_uint(ha[4]);
        uint32_t a3 = __float_as_uint(ha[8 * SST + 4]);
        const float* wb0 = Ws + (k0 + tig) * SST + gID;
        #pragma unroll
        for (int j = 0; j < 12; j++) {
            uint32_t b0 = __float_as_uint(wb0[j * 8]);
            uint32_t b1 = __float_as_uint(wb0[j * 8 + 4 * SST]);
            asm volatile(
                "mma.sync.aligned.m16n8k8.row.col.f32.tf32.tf32.f32 "
                "{%0,%1,%2,%3}, {%4,%5,%6,%7}, {%8,%9}, {%0,%1,%2,%3};"
                : "+f"(c[j][0]), "+f"(c[j][1]), "+f"(c[j][2]), "+f"(c[j][3])
                : "r"(a0), "r"(a1), "r"(a2), "r"(a3), "r"(b0), "r"(b1));
        }
    }

    // epilogue: scale by dis[r], store float2 pairs
    int row0 = r0 + wm + gID;
    int row1 = row0 + 8;
    float d0 = (row0 < N_NODES) ? g_dis[row0] : 0.0f;
    float d1 = (row1 < N_NODES) ? g_dis[row1] : 0.0f;
    #pragma unroll
    for (int j = 0; j < 12; j++) {
        int col = j * 8 + tig * 2;
        if (row0 < N_NODES)
            *(float2*)(g_tmp + (size_t)row0 * HID + col) =
                make_float2(c[j][0] * d0, c[j][1] * d0);
        if (row1 < N_NODES)
            *(float2*)(g_tmp + (size_t)row1 * HID + col) =
                make_float2(c[j][2] * d1, c[j][3] * d1);
    }
}

// ---------------- 6. gather: out[c] = b + dis[c] * (tmp[c] + sum_in tmp[src]) ----------------
__global__ __launch_bounds__(256) void gather_kernel(
    const float* __restrict__ b, int out_sel)
{
    float* out = buf_ptr(out_sel);
    int c    = (blockIdx.x * blockDim.x + threadIdx.x) >> 5;
    int lane = threadIdx.x & 31;
    if (c >= N_NODES || lane >= 24) return;

    int beg = g_rowptr[c];
    int end = g_rowptr[c + 1];

    float4 acc  = ((const float4*)g_tmp)[c * 24 + lane];   // self term
    float4 acc2 = make_float4(0.f, 0.f, 0.f, 0.f);

    int e = beg;
    for (; e + 1 < end; e += 2) {
        int r0 = __ldg(&g_srcs[e]);
        int r1 = __ldg(&g_srcs[e + 1]);
        float4 v0 = ((const float4*)g_tmp)[r0 * 24 + lane];
        float4 v1 = ((const float4*)g_tmp)[r1 * 24 + lane];
        acc.x  += v0.x; acc.y  += v0.y; acc.z  += v0.z; acc.w  += v0.w;
        acc2.x += v1.x; acc2.y += v1.y; acc2.z += v1.z; acc2.w += v1.w;
    }
    if (e < end) {
        int r0 = __ldg(&g_srcs[e]);
        float4 v0 = ((const float4*)g_tmp)[r0 * 24 + lane];
        acc.x += v0.x; acc.y += v0.y; acc.z += v0.z; acc.w += v0.w;
    }
    acc.x += acc2.x; acc.y += acc2.y; acc.z += acc2.z; acc.w += acc2.w;

    float  d  = g_dis[c];
    float4 bb = ((const float4*)b)[lane];
    ((float4*)out)[c * 24 + lane] =
        make_float4(bb.x + d * acc.x, bb.y + d * acc.y,
                    bb.z + d * acc.z, bb.w + d * acc.w);
}

// ---------------- 7. mean-pool accumulation (relu fused) ----------------
__global__ __launch_bounds__(256) void pool_kernel(const int* __restrict__ batch)
{
    int n    = (blockIdx.x * blockDim.x + threadIdx.x) >> 5;
    int lane = threadIdx.x & 31;
    if (n >= N_NODES) return;
    int g = batch[n];
    if (lane < 24) {
        float4 v = ((const float4*)g_bufA)[n * 24 + lane];
        float* dst = g_pool + g * HID + lane * 4;
        atomicAdd(dst + 0, fmaxf(v.x, 0.0f));
        atomicAdd(dst + 1, fmaxf(v.y, 0.0f));
        atomicAdd(dst + 2, fmaxf(v.z, 0.0f));
        atomicAdd(dst + 3, fmaxf(v.w, 0.0f));
    } else if (lane == 24) {
        atomicAdd(&g_cnt[g], 1.0f);
    }
}

// ---------------- 8. final: out = (pool / max(cnt,1)) @ fc_w + fc_b ----------------
__global__ __launch_bounds__(256) void final_kernel(
    const float* __restrict__ fc_w, const float* __restrict__ fc_b,
    float* __restrict__ out)
{
    int t = blockIdx.x * blockDim.x + threadIdx.x;   // 8192
    if (t >= N_GRAPHS * OUT_DIM) return;
    int g = t >> 5;
    int o = t & 31;
    float inv = 1.0f / fmaxf(g_cnt[g], 1.0f);
    float acc = fc_b[o];
    #pragma unroll 8
    for (int f = 0; f < HID; f++)
        acc = fmaf(g_pool[g * HID + f] * inv, fc_w[f * OUT_DIM + o], acc);
    out[t] = acc;
}

// ---------------- launch ----------------
extern "C" void kernel_launch(void* const* d_in, const int* in_sizes, int n_in,
                              void* d_out, int out_size)
{
    const float* x    = (const float*)d_in[0];
    const int*   ei   = (const int*)d_in[1];   // [2, E] int32
    const int*   bat  = (const int*)d_in[2];   // [N] int32
    const float* W1   = (const float*)d_in[3];
    const float* b1   = (const float*)d_in[4];
    const float* W2   = (const float*)d_in[5];
    const float* b2   = (const float*)d_in[6];
    const float* W3   = (const float*)d_in[7];
    const float* b3   = (const float*)d_in[8];
    const float* fc_w = (const float*)d_in[9];
    const float* fc_b = (const float*)d_in[10];
    float* out = (float*)d_out;

    const int* erow = ei;
    const int* ecol = ei + N_EDGES;

    static bool attr_set = false;
    if (!attr_set) {
        cudaFuncSetAttribute(gemm_kernel,
                             cudaFuncAttributeMaxDynamicSharedMemorySize, GEMM_SMEM);
        attr_set = true;
    }

    // CSR build + normalization
    zero_kernel<<<(N_NODES + 255) / 256, 256>>>();
    hist_kernel<<<(N_EDGES + 255) / 256, 256>>>(ecol);
    scan_kernel<<<1, 1024>>>();
    fill_kernel<<<(N_EDGES + 255) / 256, 256>>>(erow, ecol);

    const int gemm_grid  = (N_NODES + GMR - 1) / GMR;   // 391
    const int node_warps = (N_NODES * 32 + 255) / 256;

    // layer 1: x -> bufA
    gemm_kernel<<<gemm_grid, GMT, GEMM_SMEM>>>(x, 0, W1, 0);
    gather_kernel<<<node_warps, 256>>>(b1, 1);
    // layer 2: relu(bufA) -> bufB
    gemm_kernel<<<gemm_grid, GMT, GEMM_SMEM>>>(nullptr, 1, W2, 1);
    gather_kernel<<<node_warps, 256>>>(b2, 2);
    // layer 3: relu(bufB) -> bufA
    gemm_kernel<<<gemm_grid, GMT, GEMM_SMEM>>>(nullptr, 2, W3, 1);
    gather_kernel<<<node_warps, 256>>>(b3, 1);

    // mean pool (relu fused) + FC
    pool_kernel<<<node_warps, 256>>>(bat);
    final_kernel<<<(N_GRAPHS * OUT_DIM + 255) / 256, 256>>>(fc_w, fc_b, out);
}

// round 7
// speedup vs baseline: 3.2238x; 1.0187x over previous
#include <cuda_runtime.h>
#include <cuda_bf16.h>
#include <cstdint>

#define N_NODES  50000
#define N_EDGES  800000
#define HID      96
#define OUT_DIM  32
#define N_GRAPHS 256

// ---------------- scratch (static device globals; no allocation) ----------------
__device__ __align__(128) float g_dis[N_NODES];            // d^{-1/2}
__device__ __align__(128) float g_tmp [N_NODES * HID];     // (h @ W) * dis[r]
__device__ __align__(128) float g_bufA[N_NODES * HID];     // layer outputs (ping)
__device__ __align__(128) float g_bufB[N_NODES * HID];     // layer outputs (pong)
__device__ __align__(128) float g_pool[N_GRAPHS * HID];    // per-graph feature sums
__device__ __align__(128) float g_cnt [N_GRAPHS];          // per-graph node counts
// CSR (edges grouped by target/col)
__device__ __align__(128) int g_cntin [N_NODES];
__device__ __align__(128) int g_rowptr[N_NODES + 1];
__device__ __align__(128) int g_cursor[N_NODES];
__device__ __align__(128) int g_srcs  [N_EDGES];

__device__ __forceinline__ float* buf_ptr(int sel) {
    return (sel == 1) ? g_bufA : g_bufB;
}

__device__ __forceinline__ float to_tf32(float x) {
    uint32_t r;
    asm("cvt.rna.tf32.f32 %0, %1;" : "=r"(r) : "f"(x));
    return __uint_as_float(r);
}

// ---------------- 1. zero counters ----------------
__global__ void zero_kernel() {
    int i = blockIdx.x * blockDim.x + threadIdx.x;
    if (i < N_NODES) g_cntin[i] = 0;
    if (i < N_GRAPHS * HID) g_pool[i] = 0.0f;
    if (i < N_GRAPHS) g_cnt[i] = 0.0f;
}

// ---------------- 2. histogram of targets ----------------
__global__ void hist_kernel(const int* __restrict__ col) {
    int e = blockIdx.x * blockDim.x + threadIdx.x;
    if (e < N_EDGES) atomicAdd(&g_cntin[col[e]], 1);
}

// ---------------- 3. single-block exclusive scan (int4-vectorized) ----------------
__global__ __launch_bounds__(1024) void scan_kernel() {
    __shared__ int warp_sums[32];
    __shared__ int carry_s;
    const int tid  = threadIdx.x;
    const int lane = tid & 31;
    const int wid  = tid >> 5;
    if (tid == 0) carry_s = 0;
    __syncthreads();

    const int NV4 = N_NODES / 4;   // 12500
    for (int base = 0; base < NV4; base += 1024) {
        int i4 = base + tid;
        int4 v = make_int4(0, 0, 0, 0);
        if (i4 < NV4) v = ((const int4*)g_cntin)[i4];
        int t = v.x + v.y + v.z + v.w;
        int x = t;
        #pragma unroll
        for (int o = 1; o < 32; o <<= 1) {
            int y = __shfl_up_sync(0xFFFFFFFFu, x, o);
            if (lane >= o) x += y;
        }
        if (lane == 31) warp_sums[wid] = x;
        __syncthreads();
        if (wid == 0) {
            int s = warp_sums[lane];
            #pragma unroll
            for (int o = 1; o < 32; o <<= 1) {
                int y = __shfl_up_sync(0xFFFFFFFFu, s, o);
                if (lane >= o) s += y;
            }
            warp_sums[lane] = s;
        }
        __syncthreads();
        int excl = carry_s + ((wid == 0) ? 0 : warp_sums[wid - 1]) + x - t;
        if (i4 < NV4) {
            int e0 = excl, e1 = e0 + v.x, e2 = e1 + v.y, e3 = e2 + v.z;
            ((int4*)g_rowptr)[i4] = make_int4(e0, e1, e2, e3);
            ((int4*)g_cursor)[i4] = make_int4(e0, e1, e2, e3);
            ((float4*)g_dis)[i4]  = make_float4(rsqrtf(1.0f + (float)v.x),
                                                rsqrtf(1.0f + (float)v.y),
                                                rsqrtf(1.0f + (float)v.z),
                                                rsqrtf(1.0f + (float)v.w));
        }
        __syncthreads();
        if (tid == 0) carry_s += warp_sums[31];
        __syncthreads();
    }
    if (tid == 0) g_rowptr[N_NODES] = carry_s;
}

// ---------------- 4. fill CSR slots ----------------
__global__ void fill_kernel(const int* __restrict__ row, const int* __restrict__ col) {
    int e = blockIdx.x * blockDim.x + threadIdx.x;
    if (e >= N_EDGES) return;
    int p = atomicAdd(&g_cursor[col[e]], 1);
    g_srcs[p] = row[e];
}

// ---------------- 5. tf32 MMA GEMM: tmp = (act(in) @ W) * dis[r] ----------------
#define GMT 256
#define GMR 128
#define SST 104                                       // smem row stride (floats)
#define GEMM_SMEM ((HID + GMR) * SST * 4)             // 93184 B
__global__ __launch_bounds__(GMT) void gemm_kernel(
    const float* __restrict__ xin, int in_sel,
    const float* __restrict__ W, int relu_in)
{
    extern __shared__ float smem[];
    float* Ws = smem;              // [96][104]
    float* hs = smem + HID * SST;  // [128][104]
    const float* in = (in_sel == 0) ? xin : buf_ptr(in_sel);

    const int tid = threadIdx.x;
    const int r0  = blockIdx.x * GMR;

    #pragma unroll
    for (int i4 = tid; i4 < HID * (HID / 4); i4 += GMT) {
        int r = i4 / (HID / 4), c4 = i4 % (HID / 4);
        float4 v = ((const float4*)W)[i4];
        float* d = Ws + r * SST + c4 * 4;
        d[0] = to_tf32(v.x); d[1] = to_tf32(v.y);
        d[2] = to_tf32(v.z); d[3] = to_tf32(v.w);
    }
    #pragma unroll
    for (int i4 = tid; i4 < GMR * (HID / 4); i4 += GMT) {
        int r = i4 / (HID / 4), c4 = i4 % (HID / 4);
        float4 v = make_float4(0.f, 0.f, 0.f, 0.f);
        if (r0 + r < N_NODES) v = ((const float4*)(in + (size_t)(r0 + r) * HID))[c4];
        if (relu_in) {
            v.x = fmaxf(v.x, 0.f); v.y = fmaxf(v.y, 0.f);
            v.z = fmaxf(v.z, 0.f); v.w = fmaxf(v.w, 0.f);
        }
        float* d = hs + r * SST + c4 * 4;
        d[0] = to_tf32(v.x); d[1] = to_tf32(v.y);
        d[2] = to_tf32(v.z); d[3] = to_tf32(v.w);
    }
    __syncthreads();

    const int warp = tid >> 5;
    const int lane = tid & 31;
    const int gID  = lane >> 2;
    const int tig  = lane & 3;
    const int wm   = warp * 16;

    float c[12][4];
    #pragma unroll
    for (int j = 0; j < 12; j++)
        #pragma unroll
        for (int q = 0; q < 4; q++) c[j][q] = 0.0f;

    #pragma unroll
    for (int k0 = 0; k0 < HID; k0 += 8) {
        const float* ha = hs + (wm + gID) * SST + k0 + tig;
        uint32_t a0 = __float_as_uint(ha[0]);
        uint32_t a1 = __float_as_uint(ha[8 * SST]);
        uint32_t a2 = __float_as_uint(ha[4]);
        uint32_t a3 = __float_as_uint(ha[8 * SST + 4]);
        const float* wb0 = Ws + (k0 + tig) * SST + gID;
        #pragma unroll
        for (int j = 0; j < 12; j++) {
            uint32_t b0 = __float_as_uint(wb0[j * 8]);
            uint32_t b1 = __float_as_uint(wb0[j * 8 + 4 * SST]);
            asm volatile(
                "mma.sync.aligned.m16n8k8.row.col.f32.tf32.tf32.f32 "
                "{%0,%1,%2,%3}, {%4,%5,%6,%7}, {%8,%9}, {%0,%1,%2,%3};"
                : "+f"(c[j][0]), "+f"(c[j][1]), "+f"(c[j][2]), "+f"(c[j][3])
                : "r"(a0), "r"(a1), "r"(a2), "r"(a3), "r"(b0), "r"(b1));
        }
    }

    int row0 = r0 + wm + gID;
    int row1 = row0 + 8;
    float d0 = (row0 < N_NODES) ? g_dis[row0] : 0.0f;
    float d1 = (row1 < N_NODES) ? g_dis[row1] : 0.0f;
    #pragma unroll
    for (int j = 0; j < 12; j++) {
        int col = j * 8 + tig * 2;
        if (row0 < N_NODES)
            *(float2*)(g_tmp + (size_t)row0 * HID + col) =
                make_float2(c[j][0] * d0, c[j][1] * d0);
        if (row1 < N_NODES)
            *(float2*)(g_tmp + (size_t)row1 * HID + col) =
                make_float2(c[j][2] * d1, c[j][3] * d1);
    }
}

// ---------------- 6. gather: out[c] = b + dis[c] * (tmp[c] + sum_in tmp[src]) ----------------
// unroll-4 with 4 accumulators for MLP. If batch != nullptr: fused relu+pool epilogue.
__global__ __launch_bounds__(256) void gather_kernel(
    const float* __restrict__ b, int out_sel, const int* __restrict__ batch)
{
    int c    = (blockIdx.x * blockDim.x + threadIdx.x) >> 5;
    int lane = threadIdx.x & 31;
    if (c >= N_NODES) return;

    int g = 0;
    if (batch) g = batch[c];
    if (lane >= 24) {
        if (batch && lane == 24) atomicAdd(&g_cnt[g], 1.0f);
        return;
    }

    int beg = g_rowptr[c];
    int end = g_rowptr[c + 1];

    const float4* T = (const float4*)g_tmp;
    float4 a0 = T[c * 24 + lane];   // self term
    float4 a1 = make_float4(0.f, 0.f, 0.f, 0.f);
    float4 a2 = make_float4(0.f, 0.f, 0.f, 0.f);
    float4 a3 = make_float4(0.f, 0.f, 0.f, 0.f);

    int e = beg;
    for (; e + 4 <= end; e += 4) {
        int r0 = __ldg(&g_srcs[e]);
        int r1 = __ldg(&g_srcs[e + 1]);
        int r2 = __ldg(&g_srcs[e + 2]);
        int r3 = __ldg(&g_srcs[e + 3]);
        float4 v0 = T[r0 * 24 + lane];
        float4 v1 = T[r1 * 24 + lane];
        float4 v2 = T[r2 * 24 + lane];
        float4 v3 = T[r3 * 24 + lane];
        a0.x += v0.x; a0.y += v0.y; a0.z += v0.z; a0.w += v0.w;
        a1.x += v1.x; a1.y += v1.y; a1.z += v1.z; a1.w += v1.w;
        a2.x += v2.x; a2.y += v2.y; a2.z += v2.z; a2.w += v2.w;
        a3.x += v3.x; a3.y += v3.y; a3.z += v3.z; a3.w += v3.w;
    }
    for (; e < end; e++) {
        int r = __ldg(&g_srcs[e]);
        float4 v = T[r * 24 + lane];
        a0.x += v.x; a0.y += v.y; a0.z += v.z; a0.w += v.w;
    }
    a0.x += a1.x + a2.x + a3.x;
    a0.y += a1.y + a2.y + a3.y;
    a0.z += a1.z + a2.z + a3.z;
    a0.w += a1.w + a2.w + a3.w;

    float  d  = g_dis[c];
    float4 bb = ((const float4*)b)[lane];
    float4 o  = make_float4(bb.x + d * a0.x, bb.y + d * a0.y,
                            bb.z + d * a0.z, bb.w + d * a0.w);
    if (!batch) {
        ((float4*)buf_ptr(out_sel))[c * 24 + lane] = o;
    } else {
        float* dst = g_pool + g * HID + lane * 4;
        atomicAdd(dst + 0, fmaxf(o.x, 0.0f));
        atomicAdd(dst + 1, fmaxf(o.y, 0.0f));
        atomicAdd(dst + 2, fmaxf(o.z, 0.0f));
        atomicAdd(dst + 3, fmaxf(o.w, 0.0f));
    }
}

// ---------------- 7. final: out = (pool / max(cnt,1)) @ fc_w + fc_b ----------------
__global__ __launch_bounds__(256) void final_kernel(
    const float* __restrict__ fc_w, const float* __restrict__ fc_b,
    float* __restrict__ out)
{
    int t = blockIdx.x * blockDim.x + threadIdx.x;   // 8192
    if (t >= N_GRAPHS * OUT_DIM) return;
    int g = t >> 5;
    int o = t & 31;
    float inv = 1.0f / fmaxf(g_cnt[g], 1.0f);
    float acc = fc_b[o];
    #pragma unroll 8
    for (int f = 0; f < HID; f++)
        acc = fmaf(g_pool[g * HID + f] * inv, fc_w[f * OUT_DIM + o], acc);
    out[t] = acc;
}

// ---------------- launch ----------------
extern "C" void kernel_launch(void* const* d_in, const int* in_sizes, int n_in,
                              void* d_out, int out_size)
{
    const float* x    = (const float*)d_in[0];
    const int*   ei   = (const int*)d_in[1];   // [2, E] int32
    const int*   bat  = (const int*)d_in[2];   // [N] int32
    const float* W1   = (const float*)d_in[3];
    const float* b1   = (const float*)d_in[4];
    const float* W2   = (const float*)d_in[5];
    const float* b2   = (const float*)d_in[6];
    const float* W3   = (const float*)d_in[7];
    const float* b3   = (const float*)d_in[8];
    const float* fc_w = (const float*)d_in[9];
    const float* fc_b = (const float*)d_in[10];
    float* out = (float*)d_out;

    const int* erow = ei;
    const int* ecol = ei + N_EDGES;

    static cudaStream_t s_side = nullptr;
    static cudaEvent_t  s_ev1 = nullptr, s_ev2 = nullptr;
    if (!s_side) {
        cudaFuncSetAttribute(gemm_kernel,
                             cudaFuncAttributeMaxDynamicSharedMemorySize, GEMM_SMEM);
        cudaStreamCreateWithFlags(&s_side, cudaStreamNonBlocking);
        cudaEventCreateWithFlags(&s_ev1, cudaEventDisableTiming);
        cudaEventCreateWithFlags(&s_ev2, cudaEventDisableTiming);
    }

    const int gemm_grid  = (N_NODES + GMR - 1) / GMR;   // 391
    const int node_warps = (N_NODES * 32 + 255) / 256;

    // CSR build prefix (gemm1 needs g_dis from scan; fill is independent of gemm1)
    zero_kernel<<<(N_NODES + 255) / 256, 256>>>();
    hist_kernel<<<(N_EDGES + 255) / 256, 256>>>(ecol);
    scan_kernel<<<1, 1024>>>();

    // fork: gemm1 on side stream, fill on main stream
    cudaEventRecord(s_ev1, 0);
    cudaStreamWaitEvent(s_side, s_ev1, 0);
    gemm_kernel<<<gemm_grid, GMT, GEMM_SMEM, s_side>>>(x, 0, W1, 0);
    cudaEventRecord(s_ev2, s_side);
    fill_kernel<<<(N_EDGES + 255) / 256, 256>>>(erow, ecol);
    cudaStreamWaitEvent(0, s_ev2, 0);

    // layer 1 gather: -> bufA
    gather_kernel<<<node_warps, 256>>>(b1, 1, nullptr);
    // layer 2: relu(bufA) -> bufB
    gemm_kernel<<<gemm_grid, GMT, GEMM_SMEM>>>(nullptr, 1, W2, 1);
    gather_kernel<<<node_warps, 256>>>(b2, 2, nullptr);
    // layer 3: relu(bufB) -> pool (fused)
    gemm_kernel<<<gemm_grid, GMT, GEMM_SMEM>>>(nullptr, 2, W3, 1);
    gather_kernel<<<node_warps, 256>>>(b3, 0, bat);

    // FC
    final_kernel<<<(N_GRAPHS * OUT_DIM + 255) / 256, 256>>>(fc_w, fc_b, out);
}